// round 1
// baseline (speedup 1.0000x reference)
#include <cuda_runtime.h>
#include <cuda_bf16.h>
#include <cstddef>

// MLPLinkPredictor:
//   e = [h[src]; h[dst]]  (E x 512)
//   hid = relu(e @ W1_w.T + b1)   (E x 256)
//   score = hid @ W2_w.T + b2     (E)
//
// Restructured: W1 = [A | B], precompute per-node
//   ucat[n, 0:256]   = A @ h[n] + b1
//   ucat[n, 256:512] = B @ h[n]
// then per edge: score = w2 . relu(ucat[s,0:256] + ucat[d,256:512]) + b2

#define NNODES 50000
#define NFEAT  256
#define NOUT   512   // 2*NFEAT (u and v concatenated)

// Scratch: per-node precomputed [u ; v], 50000 x 512 f32 = 102.4 MB
__device__ float g_ucat[(size_t)NNODES * NOUT];
// Reshaped weights: Wt[j][k], j in [0,512), k in [0,256)
//   j < 256 : Wt[j][k] = W1_w[j*512 + k]          (A)
//   j >= 256: Wt[j][k] = W1_w[(j-256)*512+256+k]  (B)
__device__ float g_wt[NOUT * NFEAT];

// ---------------------------------------------------------------------------
// Weight reshape: 512*256 = 131072 elements
// ---------------------------------------------------------------------------
__global__ void reshape_w_kernel(const float* __restrict__ W1) {
    int idx = blockIdx.x * blockDim.x + threadIdx.x;
    if (idx >= NOUT * NFEAT) return;
    int j = idx >> 8;          // 0..511
    int k = idx & 255;         // 0..255
    g_wt[idx] = W1[(j & 255) * 512 + ((j >> 8) << 8) + k];
}

// ---------------------------------------------------------------------------
// Node GEMM: g_ucat[n, j] = sum_k h[n,k] * Wt[j,k]  (+ b1[j] if j < 256)
// Tiled fp32 GEMM, BM=BN=64, BK=16, 256 threads, 4x4 register tile/thread.
// ---------------------------------------------------------------------------
#define BM 64
#define BN 64
#define BK 16

__global__ __launch_bounds__(256) void node_gemm_kernel(
    const float* __restrict__ h, const float* __restrict__ b1)
{
    __shared__ float As[BK][BM + 4];
    __shared__ float Bs[BK][BN + 4];

    const int tid = threadIdx.x;       // 0..255
    const int tx = tid & 15;           // N micro-tile index
    const int ty = tid >> 4;           // M micro-tile index
    const int m0 = blockIdx.y * BM;
    const int n0 = blockIdx.x * BN;

    // Loader mapping: each thread loads one float4 per tile
    const int lrow = tid >> 2;         // 0..63
    const int lk4  = (tid & 3) << 2;   // 0,4,8,12

    float acc[4][4] = {};

    for (int k0 = 0; k0 < NFEAT; k0 += BK) {
        // Load A tile (h), guarded on M
        int arow = m0 + lrow;
        float4 av;
        if (arow < NNODES)
            av = *reinterpret_cast<const float4*>(h + (size_t)arow * NFEAT + k0 + lk4);
        else
            av = make_float4(0.f, 0.f, 0.f, 0.f);
        As[lk4 + 0][lrow] = av.x;
        As[lk4 + 1][lrow] = av.y;
        As[lk4 + 2][lrow] = av.z;
        As[lk4 + 3][lrow] = av.w;

        // Load B tile (Wt) — N=512 exact multiple, no guard needed
        int brow = n0 + lrow;
        float4 bv = *reinterpret_cast<const float4*>(g_wt + (size_t)brow * NFEAT + k0 + lk4);
        Bs[lk4 + 0][lrow] = bv.x;
        Bs[lk4 + 1][lrow] = bv.y;
        Bs[lk4 + 2][lrow] = bv.z;
        Bs[lk4 + 3][lrow] = bv.w;

        __syncthreads();

        #pragma unroll
        for (int k = 0; k < BK; k++) {
            float4 a = *reinterpret_cast<const float4*>(&As[k][ty * 4]);
            float4 b = *reinterpret_cast<const float4*>(&Bs[k][tx * 4]);
            acc[0][0] += a.x * b.x; acc[0][1] += a.x * b.y; acc[0][2] += a.x * b.z; acc[0][3] += a.x * b.w;
            acc[1][0] += a.y * b.x; acc[1][1] += a.y * b.y; acc[1][2] += a.y * b.z; acc[1][3] += a.y * b.w;
            acc[2][0] += a.z * b.x; acc[2][1] += a.z * b.y; acc[2][2] += a.z * b.z; acc[2][3] += a.z * b.w;
            acc[3][0] += a.w * b.x; acc[3][1] += a.w * b.y; acc[3][2] += a.w * b.z; acc[3][3] += a.w * b.w;
        }

        __syncthreads();
    }

    // Epilogue: add b1 to the u half (cols < 256), store to g_ucat
    #pragma unroll
    for (int i = 0; i < 4; i++) {
        int row = m0 + ty * 4 + i;
        if (row >= NNODES) continue;
        #pragma unroll
        for (int j = 0; j < 4; j++) {
            int col = n0 + tx * 4 + j;
            float bias = (col < NFEAT) ? b1[col] : 0.f;
            g_ucat[(size_t)row * NOUT + col] = acc[i][j] + bias;
        }
    }
}

// ---------------------------------------------------------------------------
// Edge kernel: out[e] = b2 + sum_o w2[o] * relu(u[src[e]][o] + v[dst[e]][o])
// One warp per edge (grid-stride); each lane handles 8 contiguous features.
// w2 preloaded into registers once per thread.
// ---------------------------------------------------------------------------
__global__ __launch_bounds__(256) void edge_kernel(
    const int* __restrict__ src, const int* __restrict__ dst,
    const float* __restrict__ w2, const float* __restrict__ b2p,
    float* __restrict__ out, int E)
{
    const int lane = threadIdx.x & 31;
    const int warp_global = (blockIdx.x * blockDim.x + threadIdx.x) >> 5;
    const int nwarps = (gridDim.x * blockDim.x) >> 5;

    // Preload w2 slice for this lane (features lane*8 .. lane*8+7)
    const float4* w2v = reinterpret_cast<const float4*>(w2);
    float4 w0 = w2v[lane * 2 + 0];
    float4 w1 = w2v[lane * 2 + 1];
    float b2 = *b2p;

    for (int e = warp_global; e < E; e += nwarps) {
        int s = src[e];
        int d = dst[e];
        const float4* pu = reinterpret_cast<const float4*>(g_ucat + (size_t)s * NOUT) + lane * 2;
        const float4* pv = reinterpret_cast<const float4*>(g_ucat + (size_t)d * NOUT + NFEAT) + lane * 2;
        float4 a0 = pu[0];
        float4 a1 = pu[1];
        float4 c0 = pv[0];
        float4 c1 = pv[1];

        float sum;
        sum  = w0.x * fmaxf(a0.x + c0.x, 0.f);
        sum += w0.y * fmaxf(a0.y + c0.y, 0.f);
        sum += w0.z * fmaxf(a0.z + c0.z, 0.f);
        sum += w0.w * fmaxf(a0.w + c0.w, 0.f);
        sum += w1.x * fmaxf(a1.x + c1.x, 0.f);
        sum += w1.y * fmaxf(a1.y + c1.y, 0.f);
        sum += w1.z * fmaxf(a1.z + c1.z, 0.f);
        sum += w1.w * fmaxf(a1.w + c1.w, 0.f);

        #pragma unroll
        for (int o = 16; o > 0; o >>= 1)
            sum += __shfl_xor_sync(0xFFFFFFFFu, sum, o);

        if (lane == 0)
            out[e] = sum + b2;
    }
}

// ---------------------------------------------------------------------------
// Launch
// ---------------------------------------------------------------------------
extern "C" void kernel_launch(void* const* d_in, const int* in_sizes, int n_in,
                              void* d_out, int out_size)
{
    const float* h    = (const float*)d_in[0];   // [50000, 256]
    const int*   src  = (const int*)  d_in[1];   // [800000]
    const int*   dst  = (const int*)  d_in[2];   // [800000]
    const float* W1_w = (const float*)d_in[3];   // [256, 512]
    const float* W1_b = (const float*)d_in[4];   // [256]
    const float* W2_w = (const float*)d_in[5];   // [1, 256] -> 256 floats
    const float* W2_b = (const float*)d_in[6];   // [1]
    float* out = (float*)d_out;
    const int E = in_sizes[1];

    // 1) Reshape weights into [512, 256] K-contiguous layout
    reshape_w_kernel<<<(NOUT * NFEAT + 255) / 256, 256>>>(W1_w);

    // 2) Per-node GEMM: ucat = h @ Wt^T (+ b1 on u half)
    dim3 ggrid(NOUT / BN, (NNODES + BM - 1) / BM);
    node_gemm_kernel<<<ggrid, 256>>>(h, W1_b);

    // 3) Per-edge score
    edge_kernel<<<2048, 256>>>(src, dst, W2_w, W2_b, out, E);
}

// round 7
// speedup vs baseline: 1.5936x; 1.5936x over previous
#include <cuda_runtime.h>
#include <cuda_bf16.h>
#include <cstdint>
#include <cstddef>

// MLPLinkPredictor, restructured:
//   W1 = [A | B]; per-node u = A h + b1, v = B h. Per edge:
//   score = w2 . relu(u[src] + v[dst]) + b2.
// Node GEMM via mma.sync bf16 (HMMA; sm_103 base target — tcgen05 is not
// available in this build) with a 3-term bf16 split (hi*hi + hi*lo + lo*hi)
// fused as one K=768 GEMM for fp32-level accuracy.

#define NNODES 50000
#define NFEAT  256
#define NOUT   512   // 2*NFEAT

// ---------------------------------------------------------------------------
// Device scratch
// ---------------------------------------------------------------------------
__device__ __align__(256) float g_ucat[(size_t)NNODES * NOUT];        // 102.4 MB
__device__ __align__(256) __nv_bfloat16 g_h_hi[(size_t)NNODES * NFEAT];
__device__ __align__(256) __nv_bfloat16 g_h_lo[(size_t)NNODES * NFEAT];
__device__ __align__(256) __nv_bfloat16 g_w_hi[NOUT * NFEAT];  // Wt[j][k]
__device__ __align__(256) __nv_bfloat16 g_w_lo[NOUT * NFEAT];

__device__ __forceinline__ uint32_t smem_u32(const void* p) {
    uint32_t a;
    asm("{ .reg .u64 t; cvta.to.shared.u64 t, %1; cvt.u32.u64 %0, t; }" : "=r"(a) : "l"(p));
    return a;
}

__device__ __forceinline__ void ldmatrix_x4(uint32_t& r0, uint32_t& r1, uint32_t& r2, uint32_t& r3,
                                            uint32_t addr) {
    asm volatile("ldmatrix.sync.aligned.m8n8.x4.shared.b16 {%0,%1,%2,%3}, [%4];"
                 : "=r"(r0), "=r"(r1), "=r"(r2), "=r"(r3) : "r"(addr));
}

__device__ __forceinline__ void mma_bf16(float* c, uint32_t a0, uint32_t a1, uint32_t a2, uint32_t a3,
                                         uint32_t b0, uint32_t b1) {
    asm volatile(
        "mma.sync.aligned.m16n8k16.row.col.f32.bf16.bf16.f32 "
        "{%0,%1,%2,%3}, {%4,%5,%6,%7}, {%8,%9}, {%0,%1,%2,%3};"
        : "+f"(c[0]), "+f"(c[1]), "+f"(c[2]), "+f"(c[3])
        : "r"(a0), "r"(a1), "r"(a2), "r"(a3), "r"(b0), "r"(b1));
}

// ---------------------------------------------------------------------------
// Prep: split h into bf16 hi/lo  (50000 x 256)
// ---------------------------------------------------------------------------
__global__ __launch_bounds__(256) void split_h_kernel(const float* __restrict__ h) {
    int i = blockIdx.x * blockDim.x + threadIdx.x;
    if (i >= NNODES * NFEAT / 2) return;
    float2 x = reinterpret_cast<const float2*>(h)[i];
    __nv_bfloat16 h0 = __float2bfloat16(x.x);
    __nv_bfloat16 h1 = __float2bfloat16(x.y);
    __nv_bfloat16 l0 = __float2bfloat16(x.x - __bfloat162float(h0));
    __nv_bfloat16 l1 = __float2bfloat16(x.y - __bfloat162float(h1));
    __nv_bfloat162 hp; hp.x = h0; hp.y = h1;
    __nv_bfloat162 lp; lp.x = l0; lp.y = l1;
    reinterpret_cast<__nv_bfloat162*>(g_h_hi)[i] = hp;
    reinterpret_cast<__nv_bfloat162*>(g_h_lo)[i] = lp;
}

// Prep: reshape W1 [256,512] -> Wt [512,256] (A rows then B rows) + split hi/lo
__global__ __launch_bounds__(256) void split_w_kernel(const float* __restrict__ W1) {
    int idx = blockIdx.x * blockDim.x + threadIdx.x;
    if (idx >= NOUT * NFEAT) return;
    int j = idx >> 8;   // output row 0..511
    int k = idx & 255;  // K index
    float x = W1[(j & 255) * 512 + ((j >> 8) << 8) + k];
    __nv_bfloat16 hi = __float2bfloat16(x);
    __nv_bfloat16 lo = __float2bfloat16(x - __bfloat162float(hi));
    g_w_hi[idx] = hi;
    g_w_lo[idx] = lo;
}

// ---------------------------------------------------------------------------
// Node GEMM (mma.sync bf16): D[128x128] per CTA, K' = 768 (3-term split),
// 24 chunks of KC=32, double-buffered static smem, register accumulators.
// 8 warps in 2(m) x 4(n); warp tile 64x32.
// ---------------------------------------------------------------------------
#define MT 128
#define NT 128
#define KC 32
#define NCHUNK 24          // 768 / 32
#define LDP (KC + 8)       // padded smem row, elements (80B rows)

__global__ __launch_bounds__(256, 2) void node_gemm_mma(const float* __restrict__ b1) {
    __shared__ __nv_bfloat16 smA[2][MT * LDP];
    __shared__ __nv_bfloat16 smB[2][NT * LDP];
    __shared__ float s_bias[NT];

    const int tid = threadIdx.x;
    const int wid = tid >> 5;
    const int lane = tid & 31;
    const int wm = wid >> 2;       // 0..1
    const int wn = wid & 3;        // 0..3
    const int m0 = blockIdx.y * MT;
    const int n0 = blockIdx.x * NT;

    if (tid < NT) {
        int col = n0 + tid;
        s_bias[tid] = (col < NFEAT) ? b1[col] : 0.f;
    }

    // gmem->smem loader mapping: row = tid/2 (0..127), half = tid%2 (16 bf16 = 32B)
    const int lrow = tid >> 1;
    const int lhalf = tid & 1;
    const bool arow_ok = (m0 + lrow) < NNODES;
    const size_t a_goff = (size_t)(m0 + lrow) * NFEAT + lhalf * 16;
    const size_t b_goff = (size_t)(n0 + lrow) * NFEAT + lhalf * 16;
    const int s_off = lrow * LDP + lhalf * 16;   // element offset in smem

    // term tables: chunk c -> term = c/8, kbase = (c%8)*KC
    const __nv_bfloat16* Aterm[3] = { g_h_hi, g_h_hi, g_h_lo };
    const __nv_bfloat16* Bterm[3] = { g_w_hi, g_w_lo, g_w_hi };

    // ldmatrix per-lane base offsets (element units)
    const int l7 = lane & 7;
    const int aRow = wm * 64 + l7 + ((lane & 8) ? 8 : 0);
    const int aColOff = (lane & 16) ? 8 : 0;
    const int aBase = aRow * LDP + aColOff;
    const int bRow = wn * 32 + l7 + ((lane & 16) ? 8 : 0);
    const int bColOff = (lane & 8) ? 8 : 0;
    const int bBase = bRow * LDP + bColOff;

    const uint32_t smA0 = smem_u32(&smA[0][0]);
    const uint32_t smA1 = smem_u32(&smA[1][0]);
    const uint32_t smB0 = smem_u32(&smB[0][0]);
    const uint32_t smB1 = smem_u32(&smB[1][0]);

    float acc[4][4][4];
    #pragma unroll
    for (int i = 0; i < 4; i++)
        #pragma unroll
        for (int j = 0; j < 4; j++)
            #pragma unroll
            for (int k = 0; k < 4; k++) acc[i][j][k] = 0.f;

    // ---- load chunk 0 into buffer 0 ----
    {
        const __nv_bfloat16* As = Aterm[0];
        const __nv_bfloat16* Bs = Bterm[0];
        uint4 a0 = make_uint4(0,0,0,0), a1 = make_uint4(0,0,0,0);
        if (arow_ok) {
            const uint4* gp = reinterpret_cast<const uint4*>(As + a_goff);
            a0 = gp[0]; a1 = gp[1];
        }
        const uint4* gq = reinterpret_cast<const uint4*>(Bs + b_goff);
        uint4 b0v = gq[0], b1v = gq[1];
        *reinterpret_cast<uint4*>(&smA[0][s_off])     = a0;
        *reinterpret_cast<uint4*>(&smA[0][s_off + 8]) = a1;
        *reinterpret_cast<uint4*>(&smB[0][s_off])     = b0v;
        *reinterpret_cast<uint4*>(&smB[0][s_off + 8]) = b1v;
    }
    __syncthreads();

    for (int c = 0; c < NCHUNK; c++) {
        const int buf = c & 1;
        const uint32_t sA = buf ? smA1 : smA0;
        const uint32_t sB = buf ? smB1 : smB0;

        // prefetch chunk c+1 into registers
        uint4 pa0, pa1, pb0, pb1;
        const bool have_next = (c + 1) < NCHUNK;
        if (have_next) {
            const int cn = c + 1;
            const int term = cn >> 3;
            const int kbase = (cn & 7) * KC;
            const __nv_bfloat16* As = Aterm[term];
            const __nv_bfloat16* Bs = Bterm[term];
            pa0 = make_uint4(0,0,0,0); pa1 = make_uint4(0,0,0,0);
            if (arow_ok) {
                const uint4* gp = reinterpret_cast<const uint4*>(As + a_goff + kbase);
                pa0 = gp[0]; pa1 = gp[1];
            }
            const uint4* gq = reinterpret_cast<const uint4*>(Bs + b_goff + kbase);
            pb0 = gq[0]; pb1 = gq[1];
        }

        // compute chunk c: 2 k16 steps
        #pragma unroll
        for (int kk = 0; kk < KC; kk += 16) {
            uint32_t af[4][4];
            #pragma unroll
            for (int mt = 0; mt < 4; mt++) {
                uint32_t addr = sA + (uint32_t)(aBase + mt * 16 * LDP + kk) * 2u;
                ldmatrix_x4(af[mt][0], af[mt][1], af[mt][2], af[mt][3], addr);
            }
            uint32_t bf[4][2];
            #pragma unroll
            for (int ntp = 0; ntp < 2; ntp++) {
                uint32_t addr = sB + (uint32_t)(bBase + ntp * 16 * LDP + kk) * 2u;
                uint32_t r0, r1, r2, r3;
                ldmatrix_x4(r0, r1, r2, r3, addr);
                bf[ntp * 2 + 0][0] = r0; bf[ntp * 2 + 0][1] = r1;
                bf[ntp * 2 + 1][0] = r2; bf[ntp * 2 + 1][1] = r3;
            }
            #pragma unroll
            for (int mt = 0; mt < 4; mt++)
                #pragma unroll
                for (int nt = 0; nt < 4; nt++)
                    mma_bf16(acc[mt][nt], af[mt][0], af[mt][1], af[mt][2], af[mt][3],
                             bf[nt][0], bf[nt][1]);
        }

        // stage prefetched chunk into the other buffer
        if (have_next) {
            const int nb = buf ^ 1;
            *reinterpret_cast<uint4*>(&smA[nb][s_off])     = pa0;
            *reinterpret_cast<uint4*>(&smA[nb][s_off + 8]) = pa1;
            *reinterpret_cast<uint4*>(&smB[nb][s_off])     = pb0;
            *reinterpret_cast<uint4*>(&smB[nb][s_off + 8]) = pb1;
        }
        __syncthreads();
    }

    // ---- epilogue: registers -> global, add bias ----
    const int lr = lane >> 2;           // 0..7
    const int lc = (lane & 3) * 2;      // 0,2,4,6
    #pragma unroll
    for (int mt = 0; mt < 4; mt++) {
        const int rbase = m0 + wm * 64 + mt * 16 + lr;
        #pragma unroll
        for (int nt = 0; nt < 4; nt++) {
            const int lcol = wn * 32 + nt * 8 + lc;
            const int gcol = n0 + lcol;
            const float bx = s_bias[lcol];
            const float by = s_bias[lcol + 1];
            if (rbase < NNODES) {
                float2 v; v.x = acc[mt][nt][0] + bx; v.y = acc[mt][nt][1] + by;
                *reinterpret_cast<float2*>(g_ucat + (size_t)rbase * NOUT + gcol) = v;
            }
            if (rbase + 8 < NNODES) {
                float2 v; v.x = acc[mt][nt][2] + bx; v.y = acc[mt][nt][3] + by;
                *reinterpret_cast<float2*>(g_ucat + (size_t)(rbase + 8) * NOUT + gcol) = v;
            }
        }
    }
}

// ---------------------------------------------------------------------------
// Edge kernel: out[e] = b2 + sum_o w2[o] * relu(u[src[e]][o] + v[dst[e]][o])
// Two edges per warp-iteration: 8 independent 128B loads in flight.
// ---------------------------------------------------------------------------
__global__ __launch_bounds__(256) void edge_kernel(
    const int* __restrict__ src, const int* __restrict__ dst,
    const float* __restrict__ w2, const float* __restrict__ b2p,
    float* __restrict__ out, int E)
{
    const int lane = threadIdx.x & 31;
    const int warp_global = (blockIdx.x * blockDim.x + threadIdx.x) >> 5;
    const int nwarps = (gridDim.x * blockDim.x) >> 5;

    const float4* w2v = reinterpret_cast<const float4*>(w2);
    float4 w0 = w2v[lane * 2 + 0];
    float4 w1 = w2v[lane * 2 + 1];
    float b2 = *b2p;

    for (int e = warp_global * 2; e < E; e += nwarps * 2) {
        int e1 = e + 1;
        bool has2 = (e1 < E);

        int s0 = src[e], d0 = dst[e];
        int s1 = has2 ? src[e1] : s0;
        int d1 = has2 ? dst[e1] : d0;

        const float4* pu0 = reinterpret_cast<const float4*>(g_ucat + (size_t)s0 * NOUT) + lane * 2;
        const float4* pv0 = reinterpret_cast<const float4*>(g_ucat + (size_t)d0 * NOUT + NFEAT) + lane * 2;
        const float4* pu1 = reinterpret_cast<const float4*>(g_ucat + (size_t)s1 * NOUT) + lane * 2;
        const float4* pv1 = reinterpret_cast<const float4*>(g_ucat + (size_t)d1 * NOUT + NFEAT) + lane * 2;

        float4 a00 = pu0[0], a01 = pu0[1];
        float4 c00 = pv0[0], c01 = pv0[1];
        float4 a10 = pu1[0], a11 = pu1[1];
        float4 c10 = pv1[0], c11 = pv1[1];

        float sum0;
        sum0  = w0.x * fmaxf(a00.x + c00.x, 0.f);
        sum0 += w0.y * fmaxf(a00.y + c00.y, 0.f);
        sum0 += w0.z * fmaxf(a00.z + c00.z, 0.f);
        sum0 += w0.w * fmaxf(a00.w + c00.w, 0.f);
        sum0 += w1.x * fmaxf(a01.x + c01.x, 0.f);
        sum0 += w1.y * fmaxf(a01.y + c01.y, 0.f);
        sum0 += w1.z * fmaxf(a01.z + c01.z, 0.f);
        sum0 += w1.w * fmaxf(a01.w + c01.w, 0.f);

        float sum1;
        sum1  = w0.x * fmaxf(a10.x + c10.x, 0.f);
        sum1 += w0.y * fmaxf(a10.y + c10.y, 0.f);
        sum1 += w0.z * fmaxf(a10.z + c10.z, 0.f);
        sum1 += w0.w * fmaxf(a10.w + c10.w, 0.f);
        sum1 += w1.x * fmaxf(a11.x + c11.x, 0.f);
        sum1 += w1.y * fmaxf(a11.y + c11.y, 0.f);
        sum1 += w1.z * fmaxf(a11.z + c11.z, 0.f);
        sum1 += w1.w * fmaxf(a11.w + c11.w, 0.f);

        #pragma unroll
        for (int o = 16; o > 0; o >>= 1) {
            sum0 += __shfl_xor_sync(0xFFFFFFFFu, sum0, o);
            sum1 += __shfl_xor_sync(0xFFFFFFFFu, sum1, o);
        }

        if (lane == 0) {
            out[e] = sum0 + b2;
            if (has2) out[e1] = sum1 + b2;
        }
    }
}

// ---------------------------------------------------------------------------
// Launch
// ---------------------------------------------------------------------------
extern "C" void kernel_launch(void* const* d_in, const int* in_sizes, int n_in,
                              void* d_out, int out_size)
{
    const float* h    = (const float*)d_in[0];   // [50000, 256]
    const int*   src  = (const int*)  d_in[1];   // [800000]
    const int*   dst  = (const int*)  d_in[2];   // [800000]
    const float* W1_w = (const float*)d_in[3];   // [256, 512]
    const float* W1_b = (const float*)d_in[4];   // [256]
    const float* W2_w = (const float*)d_in[5];   // [256]
    const float* W2_b = (const float*)d_in[6];   // [1]
    float* out = (float*)d_out;
    const int E = in_sizes[1];

    // 1) bf16 hi/lo splits
    split_h_kernel<<<(NNODES * NFEAT / 2 + 255) / 256, 256>>>(h);
    split_w_kernel<<<(NOUT * NFEAT + 255) / 256, 256>>>(W1_w);

    // 2) Node GEMM (HMMA): g_ucat = h @ Wt^T (+ b1 on u half)
    dim3 ggrid(NOUT / NT, (NNODES + MT - 1) / MT);
    node_gemm_mma<<<ggrid, 256>>>(W1_b);

    // 3) Per-edge scores
    edge_kernel<<<2048, 256>>>(src, dst, W2_w, W2_b, out, E);
}

// round 8
// speedup vs baseline: 2.1444x; 1.3456x over previous
#include <cuda_runtime.h>
#include <cuda_bf16.h>
#include <cuda_fp16.h>
#include <cstdint>
#include <cstddef>

// MLPLinkPredictor, restructured:
//   W1 = [A | B]; per-node u = A h + b1, v = B h. Per edge:
//   score = w2 . relu(u[src] + v[dst]) + b2.
// Node GEMM via mma.sync bf16 (3-term bf16 split, K'=768) with a cp.async
// 3-stage pipeline. Per-node activations stored fp16 (L2-resident, halves
// edge-kernel traffic; rel_err budget ~3e-4 << 1e-3).

#define NNODES 50000
#define NFEAT  256
#define NOUT   512   // 2*NFEAT

// ---------------------------------------------------------------------------
// Device scratch
// ---------------------------------------------------------------------------
__device__ __align__(256) __half g_ucat_h[(size_t)NNODES * NOUT];     // 51.2 MB
__device__ __align__(256) __nv_bfloat16 g_h_hi[(size_t)NNODES * NFEAT];
__device__ __align__(256) __nv_bfloat16 g_h_lo[(size_t)NNODES * NFEAT];
__device__ __align__(256) __nv_bfloat16 g_w_hi[NOUT * NFEAT];  // Wt[j][k]
__device__ __align__(256) __nv_bfloat16 g_w_lo[NOUT * NFEAT];

__device__ __forceinline__ uint32_t smem_u32(const void* p) {
    uint32_t a;
    asm("{ .reg .u64 t; cvta.to.shared.u64 t, %1; cvt.u32.u64 %0, t; }" : "=r"(a) : "l"(p));
    return a;
}

__device__ __forceinline__ void ldmatrix_x4(uint32_t& r0, uint32_t& r1, uint32_t& r2, uint32_t& r3,
                                            uint32_t addr) {
    asm volatile("ldmatrix.sync.aligned.m8n8.x4.shared.b16 {%0,%1,%2,%3}, [%4];"
                 : "=r"(r0), "=r"(r1), "=r"(r2), "=r"(r3) : "r"(addr));
}

__device__ __forceinline__ void mma_bf16(float* c, uint32_t a0, uint32_t a1, uint32_t a2, uint32_t a3,
                                         uint32_t b0, uint32_t b1) {
    asm volatile(
        "mma.sync.aligned.m16n8k16.row.col.f32.bf16.bf16.f32 "
        "{%0,%1,%2,%3}, {%4,%5,%6,%7}, {%8,%9}, {%0,%1,%2,%3};"
        : "+f"(c[0]), "+f"(c[1]), "+f"(c[2]), "+f"(c[3])
        : "r"(a0), "r"(a1), "r"(a2), "r"(a3), "r"(b0), "r"(b1));
}

// cp.async 16B with source-size predicate (0 -> full zero-fill)
__device__ __forceinline__ void cp16(uint32_t dst, const void* src, int nbytes) {
    asm volatile("cp.async.cg.shared.global [%0], [%1], 16, %2;"
                 :: "r"(dst), "l"(src), "r"(nbytes));
}
__device__ __forceinline__ void cp_commit() {
    asm volatile("cp.async.commit_group;" ::: "memory");
}
__device__ __forceinline__ void cp_wait1() {
    asm volatile("cp.async.wait_group 1;" ::: "memory");
}

// ---------------------------------------------------------------------------
// Prep: split h into bf16 hi/lo  (50000 x 256)
// ---------------------------------------------------------------------------
__global__ __launch_bounds__(256) void split_h_kernel(const float* __restrict__ h) {
    int i = blockIdx.x * blockDim.x + threadIdx.x;
    if (i >= NNODES * NFEAT / 2) return;
    float2 x = reinterpret_cast<const float2*>(h)[i];
    __nv_bfloat16 h0 = __float2bfloat16(x.x);
    __nv_bfloat16 h1 = __float2bfloat16(x.y);
    __nv_bfloat16 l0 = __float2bfloat16(x.x - __bfloat162float(h0));
    __nv_bfloat16 l1 = __float2bfloat16(x.y - __bfloat162float(h1));
    __nv_bfloat162 hp; hp.x = h0; hp.y = h1;
    __nv_bfloat162 lp; lp.x = l0; lp.y = l1;
    reinterpret_cast<__nv_bfloat162*>(g_h_hi)[i] = hp;
    reinterpret_cast<__nv_bfloat162*>(g_h_lo)[i] = lp;
}

// Prep: reshape W1 [256,512] -> Wt [512,256] (A rows then B rows) + split hi/lo
__global__ __launch_bounds__(256) void split_w_kernel(const float* __restrict__ W1) {
    int idx = blockIdx.x * blockDim.x + threadIdx.x;
    if (idx >= NOUT * NFEAT) return;
    int j = idx >> 8;   // output row 0..511
    int k = idx & 255;  // K index
    float x = W1[(j & 255) * 512 + ((j >> 8) << 8) + k];
    __nv_bfloat16 hi = __float2bfloat16(x);
    __nv_bfloat16 lo = __float2bfloat16(x - __bfloat162float(hi));
    g_w_hi[idx] = hi;
    g_w_lo[idx] = lo;
}

// ---------------------------------------------------------------------------
// Node GEMM (mma.sync bf16): D[128x128] per CTA, K' = 768 (3-term split),
// 24 chunks of KC=32, 3-stage cp.async pipeline, register accumulators.
// 8 warps in 2(m) x 4(n); warp tile 64x32. Output: fp16.
// ---------------------------------------------------------------------------
#define MT 128
#define NT 128
#define KC 32
#define NCHUNK 24            // 768 / 32
#define LDP (KC + 8)         // padded smem row, elements (80B rows, 16B-aligned)
#define STAGES 3
#define STAGE_ELEMS ((MT + NT) * LDP)        // 10240 elems
#define STAGE_BYTES (STAGE_ELEMS * 2)        // 20480 B
#define A_STAGE_BYTES (MT * LDP * 2)         // 10240 B
#define DYN_SMEM (STAGES * STAGE_BYTES)      // 61440 B

__global__ __launch_bounds__(256, 2) void node_gemm_mma(const float* __restrict__ b1) {
    extern __shared__ __align__(16) char dynsm[];
    __shared__ float s_bias[NT];

    const int tid = threadIdx.x;
    const int wid = tid >> 5;
    const int lane = tid & 31;
    const int wm = wid >> 2;       // 0..1
    const int wn = wid & 3;        // 0..3
    const int m0 = blockIdx.y * MT;
    const int n0 = blockIdx.x * NT;

    if (tid < NT) {
        int col = n0 + tid;
        s_bias[tid] = (col < NFEAT) ? b1[col] : 0.f;
    }

    // loader mapping: row = tid/2 (0..127), half = tid%2 (16 bf16 = 32B = 2x16B)
    const int lrow = tid >> 1;
    const int lhalf = tid & 1;
    const bool arow_ok = (m0 + lrow) < NNODES;
    const int a_nbytes = arow_ok ? 16 : 0;
    const size_t a_goff = (size_t)(m0 + lrow) * NFEAT + lhalf * 16;
    const size_t b_goff = (size_t)(n0 + lrow) * NFEAT + lhalf * 16;
    const uint32_t s_off_b = (uint32_t)(lrow * LDP + lhalf * 16) * 2u; // bytes

    const __nv_bfloat16* const Aterm[3] = { g_h_hi, g_h_hi, g_h_lo };
    const __nv_bfloat16* const Bterm[3] = { g_w_hi, g_w_lo, g_w_hi };

    const uint32_t smbase = smem_u32(dynsm);

    // ldmatrix per-lane base offsets (element units)
    const int l7 = lane & 7;
    const int aRow = wm * 64 + l7 + ((lane & 8) ? 8 : 0);
    const int aColOff = (lane & 16) ? 8 : 0;
    const uint32_t aBase_b = (uint32_t)(aRow * LDP + aColOff) * 2u;
    const int bRow = wn * 32 + l7 + ((lane & 16) ? 8 : 0);
    const int bColOff = (lane & 8) ? 8 : 0;
    const uint32_t bBase_b = (uint32_t)(bRow * LDP + bColOff) * 2u;

    float acc[4][4][4];
    #pragma unroll
    for (int i = 0; i < 4; i++)
        #pragma unroll
        for (int j = 0; j < 4; j++)
            #pragma unroll
            for (int k = 0; k < 4; k++) acc[i][j][k] = 0.f;

    // issue loads for chunk c into stage buffer (c % STAGES)
    auto issue = [&](int c) {
        const int st = c % STAGES;
        const int term = c >> 3;
        const int kbase = (c & 7) * KC;
        const uint32_t abuf = smbase + st * STAGE_BYTES;
        const uint32_t bbuf = abuf + A_STAGE_BYTES;
        const __nv_bfloat16* As = Aterm[term] + a_goff + kbase;
        const __nv_bfloat16* Bs = Bterm[term] + b_goff + kbase;
        cp16(abuf + s_off_b,      As,     a_nbytes);
        cp16(abuf + s_off_b + 16, As + 8, a_nbytes);
        cp16(bbuf + s_off_b,      Bs,     16);
        cp16(bbuf + s_off_b + 16, Bs + 8, 16);
    };

    // prologue: stages 0 and 1
    issue(0); cp_commit();
    issue(1); cp_commit();

    for (int c = 0; c < NCHUNK; c++) {
        cp_wait1();
        __syncthreads();

        // issue chunk c+2 (overwrites buffer (c-1)%3; all warps finished it)
        if (c + 2 < NCHUNK) issue(c + 2);
        cp_commit();   // unconditional: keeps group accounting uniform

        const uint32_t sA = smbase + (c % STAGES) * STAGE_BYTES;
        const uint32_t sB = sA + A_STAGE_BYTES;

        #pragma unroll
        for (int kk = 0; kk < KC; kk += 16) {
            uint32_t af[4][4];
            #pragma unroll
            for (int mt = 0; mt < 4; mt++) {
                uint32_t addr = sA + aBase_b + (uint32_t)(mt * 16 * LDP + kk) * 2u;
                ldmatrix_x4(af[mt][0], af[mt][1], af[mt][2], af[mt][3], addr);
            }
            uint32_t bf[4][2];
            #pragma unroll
            for (int ntp = 0; ntp < 2; ntp++) {
                uint32_t addr = sB + bBase_b + (uint32_t)(ntp * 16 * LDP + kk) * 2u;
                uint32_t r0, r1, r2, r3;
                ldmatrix_x4(r0, r1, r2, r3, addr);
                bf[ntp * 2 + 0][0] = r0; bf[ntp * 2 + 0][1] = r1;
                bf[ntp * 2 + 1][0] = r2; bf[ntp * 2 + 1][1] = r3;
            }
            #pragma unroll
            for (int mt = 0; mt < 4; mt++)
                #pragma unroll
                for (int nt = 0; nt < 4; nt++)
                    mma_bf16(acc[mt][nt], af[mt][0], af[mt][1], af[mt][2], af[mt][3],
                             bf[nt][0], bf[nt][1]);
        }
    }

    // ---- epilogue: registers -> fp16 global, add bias ----
    const int lr = lane >> 2;           // 0..7
    const int lc = (lane & 3) * 2;      // 0,2,4,6
    #pragma unroll
    for (int mt = 0; mt < 4; mt++) {
        const int rbase = m0 + wm * 64 + mt * 16 + lr;
        #pragma unroll
        for (int nt = 0; nt < 4; nt++) {
            const int lcol = wn * 32 + nt * 8 + lc;
            const int gcol = n0 + lcol;
            const float bx = s_bias[lcol];
            const float by = s_bias[lcol + 1];
            if (rbase < NNODES) {
                __half2 hv = __floats2half2_rn(acc[mt][nt][0] + bx, acc[mt][nt][1] + by);
                *reinterpret_cast<__half2*>(g_ucat_h + (size_t)rbase * NOUT + gcol) = hv;
            }
            if (rbase + 8 < NNODES) {
                __half2 hv = __floats2half2_rn(acc[mt][nt][2] + bx, acc[mt][nt][3] + by);
                *reinterpret_cast<__half2*>(g_ucat_h + (size_t)(rbase + 8) * NOUT + gcol) = hv;
            }
        }
    }
}

// ---------------------------------------------------------------------------
// Edge kernel (fp16 activations): out[e] = b2 + sum_o w2[o]*relu(u[s][o]+v[d][o])
// Four edges per warp-iteration: 8 independent 16B loads in flight per warp.
// ---------------------------------------------------------------------------
__device__ __forceinline__ float edge_dot(uint4 U, uint4 V, float4 w0, float4 w1) {
    float2 u0 = __half22float2(*reinterpret_cast<__half2*>(&U.x));
    float2 u1 = __half22float2(*reinterpret_cast<__half2*>(&U.y));
    float2 u2 = __half22float2(*reinterpret_cast<__half2*>(&U.z));
    float2 u3 = __half22float2(*reinterpret_cast<__half2*>(&U.w));
    float2 v0 = __half22float2(*reinterpret_cast<__half2*>(&V.x));
    float2 v1 = __half22float2(*reinterpret_cast<__half2*>(&V.y));
    float2 v2 = __half22float2(*reinterpret_cast<__half2*>(&V.z));
    float2 v3 = __half22float2(*reinterpret_cast<__half2*>(&V.w));
    float s;
    s  = w0.x * fmaxf(u0.x + v0.x, 0.f);
    s += w0.y * fmaxf(u0.y + v0.y, 0.f);
    s += w0.z * fmaxf(u1.x + v1.x, 0.f);
    s += w0.w * fmaxf(u1.y + v1.y, 0.f);
    s += w1.x * fmaxf(u2.x + v2.x, 0.f);
    s += w1.y * fmaxf(u2.y + v2.y, 0.f);
    s += w1.z * fmaxf(u3.x + v3.x, 0.f);
    s += w1.w * fmaxf(u3.y + v3.y, 0.f);
    return s;
}

__global__ __launch_bounds__(256) void edge_kernel(
    const int* __restrict__ src, const int* __restrict__ dst,
    const float* __restrict__ w2, const float* __restrict__ b2p,
    float* __restrict__ out, int E)
{
    const int lane = threadIdx.x & 31;
    const int warp_global = (blockIdx.x * blockDim.x + threadIdx.x) >> 5;
    const int nwarps = (gridDim.x * blockDim.x) >> 5;

    const float4* w2v = reinterpret_cast<const float4*>(w2);
    float4 w0 = w2v[lane * 2 + 0];
    float4 w1 = w2v[lane * 2 + 1];
    float b2 = *b2p;

    for (int e = warp_global * 4; e < E; e += nwarps * 4) {
        int n_here = min(4, E - e);
        int sx[4], dx[4];
        #pragma unroll
        for (int q = 0; q < 4; q++) {
            int ee = e + ((q < n_here) ? q : 0);
            sx[q] = src[ee];
            dx[q] = dst[ee];
        }

        uint4 U[4], V[4];
        #pragma unroll
        for (int q = 0; q < 4; q++) {
            U[q] = *(reinterpret_cast<const uint4*>(g_ucat_h + (size_t)sx[q] * NOUT) + lane);
            V[q] = *(reinterpret_cast<const uint4*>(g_ucat_h + (size_t)dx[q] * NOUT + NFEAT) + lane);
        }

        float s0 = edge_dot(U[0], V[0], w0, w1);
        float s1 = edge_dot(U[1], V[1], w0, w1);
        float s2 = edge_dot(U[2], V[2], w0, w1);
        float s3 = edge_dot(U[3], V[3], w0, w1);

        #pragma unroll
        for (int o = 16; o > 0; o >>= 1) {
            s0 += __shfl_xor_sync(0xFFFFFFFFu, s0, o);
            s1 += __shfl_xor_sync(0xFFFFFFFFu, s1, o);
            s2 += __shfl_xor_sync(0xFFFFFFFFu, s2, o);
            s3 += __shfl_xor_sync(0xFFFFFFFFu, s3, o);
        }

        if (lane == 0) {
            out[e] = s0 + b2;
            if (n_here > 1) out[e + 1] = s1 + b2;
            if (n_here > 2) out[e + 2] = s2 + b2;
            if (n_here > 3) out[e + 3] = s3 + b2;
        }
    }
}

// ---------------------------------------------------------------------------
// Launch
// ---------------------------------------------------------------------------
extern "C" void kernel_launch(void* const* d_in, const int* in_sizes, int n_in,
                              void* d_out, int out_size)
{
    const float* h    = (const float*)d_in[0];   // [50000, 256]
    const int*   src  = (const int*)  d_in[1];   // [800000]
    const int*   dst  = (const int*)  d_in[2];   // [800000]
    const float* W1_w = (const float*)d_in[3];   // [256, 512]
    const float* W1_b = (const float*)d_in[4];   // [256]
    const float* W2_w = (const float*)d_in[5];   // [256]
    const float* W2_b = (const float*)d_in[6];   // [1]
    float* out = (float*)d_out;
    const int E = in_sizes[1];

    cudaFuncSetAttribute(node_gemm_mma, cudaFuncAttributeMaxDynamicSharedMemorySize, DYN_SMEM);

    // 1) bf16 hi/lo splits
    split_h_kernel<<<(NNODES * NFEAT / 2 + 255) / 256, 256>>>(h);
    split_w_kernel<<<(NOUT * NFEAT + 255) / 256, 256>>>(W1_w);

    // 2) Node GEMM (HMMA, cp.async pipeline): g_ucat_h = fp16(h @ Wt^T + b1|0)
    dim3 ggrid(NOUT / NT, (NNODES + MT - 1) / MT);
    node_gemm_mma<<<ggrid, 256, DYN_SMEM>>>(W1_b);

    // 3) Per-edge scores
    edge_kernel<<<2048, 256>>>(src, dst, W2_w, W2_b, out, E);
}

// round 9
// speedup vs baseline: 3.3328x; 1.5542x over previous
#include <cuda_runtime.h>
#include <cuda_fp16.h>
#include <cstdint>
#include <cstddef>

// MLPLinkPredictor, restructured:
//   W1 = [A | B]; per-node u = A h + b1, v = B h. Per edge:
//   score = w2 . relu(u[src] + v[dst]) + b2.
// Node GEMM: single-term fp16 mma.sync (K=256). Error budget: fp16 GEMM
// ~4e-4 + fp16 activation storage ~2.3e-4 (measured) => ~4.6e-4 aggregate,
// under the 1e-3 threshold with 2x margin.

#define NNODES 50000
#define NFEAT  256
#define NOUT   512   // 2*NFEAT

// ---------------------------------------------------------------------------
// Device scratch
// ---------------------------------------------------------------------------
__device__ __align__(256) __half g_ucat_h[(size_t)NNODES * NOUT];     // 51.2 MB
__device__ __align__(256) __half g_h16[(size_t)NNODES * NFEAT];       // 25.6 MB
__device__ __align__(256) __half g_w16[NOUT * NFEAT];                 // Wt[j][k]

__device__ __forceinline__ uint32_t smem_u32(const void* p) {
    uint32_t a;
    asm("{ .reg .u64 t; cvta.to.shared.u64 t, %1; cvt.u32.u64 %0, t; }" : "=r"(a) : "l"(p));
    return a;
}

__device__ __forceinline__ void ldmatrix_x4(uint32_t& r0, uint32_t& r1, uint32_t& r2, uint32_t& r3,
                                            uint32_t addr) {
    asm volatile("ldmatrix.sync.aligned.m8n8.x4.shared.b16 {%0,%1,%2,%3}, [%4];"
                 : "=r"(r0), "=r"(r1), "=r"(r2), "=r"(r3) : "r"(addr));
}

__device__ __forceinline__ void mma_f16(float* c, uint32_t a0, uint32_t a1, uint32_t a2, uint32_t a3,
                                        uint32_t b0, uint32_t b1) {
    asm volatile(
        "mma.sync.aligned.m16n8k16.row.col.f32.f16.f16.f32 "
        "{%0,%1,%2,%3}, {%4,%5,%6,%7}, {%8,%9}, {%0,%1,%2,%3};"
        : "+f"(c[0]), "+f"(c[1]), "+f"(c[2]), "+f"(c[3])
        : "r"(a0), "r"(a1), "r"(a2), "r"(a3), "r"(b0), "r"(b1));
}

// cp.async 16B with source-size predicate (0 -> full zero-fill)
__device__ __forceinline__ void cp16(uint32_t dst, const void* src, int nbytes) {
    asm volatile("cp.async.cg.shared.global [%0], [%1], 16, %2;"
                 :: "r"(dst), "l"(src), "r"(nbytes));
}
__device__ __forceinline__ void cp_commit() {
    asm volatile("cp.async.commit_group;" ::: "memory");
}
__device__ __forceinline__ void cp_wait1() {
    asm volatile("cp.async.wait_group 1;" ::: "memory");
}

// ---------------------------------------------------------------------------
// Prep: h fp32 -> fp16  (50000 x 256)
// ---------------------------------------------------------------------------
__global__ __launch_bounds__(256) void conv_h_kernel(const float* __restrict__ h) {
    int i = blockIdx.x * blockDim.x + threadIdx.x;
    if (i >= NNODES * NFEAT / 2) return;
    float2 x = reinterpret_cast<const float2*>(h)[i];
    reinterpret_cast<__half2*>(g_h16)[i] = __floats2half2_rn(x.x, x.y);
}

// Prep: reshape W1 [256,512] -> Wt [512,256] (A rows then B rows), fp32->fp16
__global__ __launch_bounds__(256) void conv_w_kernel(const float* __restrict__ W1) {
    int idx = blockIdx.x * blockDim.x + threadIdx.x;
    if (idx >= NOUT * NFEAT) return;
    int j = idx >> 8;   // output row 0..511
    int k = idx & 255;  // K index
    g_w16[idx] = __float2half_rn(W1[(j & 255) * 512 + ((j >> 8) << 8) + k]);
}

// ---------------------------------------------------------------------------
// Node GEMM (mma.sync fp16): D[128x128] per CTA, K = 256,
// 8 chunks of KC=32, 3-stage cp.async pipeline, register accumulators.
// 8 warps in 2(m) x 4(n); warp tile 64x32. Output: fp16 (+bias on u half).
// ---------------------------------------------------------------------------
#define MT 128
#define NT 128
#define KC 32
#define NCHUNK 8             // 256 / 32
#define LDP (KC + 8)         // padded smem row, elements (80B rows, 16B-aligned)
#define STAGES 3
#define STAGE_ELEMS ((MT + NT) * LDP)        // 10240 elems
#define STAGE_BYTES (STAGE_ELEMS * 2)        // 20480 B
#define A_STAGE_BYTES (MT * LDP * 2)         // 10240 B
#define DYN_SMEM (STAGES * STAGE_BYTES)      // 61440 B

__global__ __launch_bounds__(256, 2) void node_gemm_mma(const float* __restrict__ b1) {
    extern __shared__ __align__(16) char dynsm[];
    __shared__ float s_bias[NT];

    const int tid = threadIdx.x;
    const int wid = tid >> 5;
    const int lane = tid & 31;
    const int wm = wid >> 2;       // 0..1
    const int wn = wid & 3;        // 0..3
    const int m0 = blockIdx.y * MT;
    const int n0 = blockIdx.x * NT;

    if (tid < NT) {
        int col = n0 + tid;
        s_bias[tid] = (col < NFEAT) ? b1[col] : 0.f;
    }

    // loader mapping: row = tid/2 (0..127), half = tid%2 (16 fp16 = 32B = 2x16B)
    const int lrow = tid >> 1;
    const int lhalf = tid & 1;
    const bool arow_ok = (m0 + lrow) < NNODES;
    const int a_nbytes = arow_ok ? 16 : 0;
    const size_t a_goff = (size_t)(m0 + lrow) * NFEAT + lhalf * 16;
    const size_t b_goff = (size_t)(n0 + lrow) * NFEAT + lhalf * 16;
    const uint32_t s_off_b = (uint32_t)(lrow * LDP + lhalf * 16) * 2u; // bytes

    const uint32_t smbase = smem_u32(dynsm);

    // ldmatrix per-lane base offsets
    const int l7 = lane & 7;
    const int aRow = wm * 64 + l7 + ((lane & 8) ? 8 : 0);
    const int aColOff = (lane & 16) ? 8 : 0;
    const uint32_t aBase_b = (uint32_t)(aRow * LDP + aColOff) * 2u;
    const int bRow = wn * 32 + l7 + ((lane & 16) ? 8 : 0);
    const int bColOff = (lane & 8) ? 8 : 0;
    const uint32_t bBase_b = (uint32_t)(bRow * LDP + bColOff) * 2u;

    float acc[4][4][4];
    #pragma unroll
    for (int i = 0; i < 4; i++)
        #pragma unroll
        for (int j = 0; j < 4; j++)
            #pragma unroll
            for (int k = 0; k < 4; k++) acc[i][j][k] = 0.f;

    auto issue = [&](int c) {
        const int st = c % STAGES;
        const int kbase = c * KC;
        const uint32_t abuf = smbase + st * STAGE_BYTES;
        const uint32_t bbuf = abuf + A_STAGE_BYTES;
        const __half* As = g_h16 + a_goff + kbase;
        const __half* Bs = g_w16 + b_goff + kbase;
        cp16(abuf + s_off_b,      As,     a_nbytes);
        cp16(abuf + s_off_b + 16, As + 8, a_nbytes);
        cp16(bbuf + s_off_b,      Bs,     16);
        cp16(bbuf + s_off_b + 16, Bs + 8, 16);
    };

    issue(0); cp_commit();
    issue(1); cp_commit();

    for (int c = 0; c < NCHUNK; c++) {
        cp_wait1();
        __syncthreads();

        if (c + 2 < NCHUNK) issue(c + 2);
        cp_commit();   // unconditional: uniform group accounting

        const uint32_t sA = smbase + (c % STAGES) * STAGE_BYTES;
        const uint32_t sB = sA + A_STAGE_BYTES;

        #pragma unroll
        for (int kk = 0; kk < KC; kk += 16) {
            uint32_t af[4][4];
            #pragma unroll
            for (int mt = 0; mt < 4; mt++) {
                uint32_t addr = sA + aBase_b + (uint32_t)(mt * 16 * LDP + kk) * 2u;
                ldmatrix_x4(af[mt][0], af[mt][1], af[mt][2], af[mt][3], addr);
            }
            uint32_t bf[4][2];
            #pragma unroll
            for (int ntp = 0; ntp < 2; ntp++) {
                uint32_t addr = sB + bBase_b + (uint32_t)(ntp * 16 * LDP + kk) * 2u;
                uint32_t r0, r1, r2, r3;
                ldmatrix_x4(r0, r1, r2, r3, addr);
                bf[ntp * 2 + 0][0] = r0; bf[ntp * 2 + 0][1] = r1;
                bf[ntp * 2 + 1][0] = r2; bf[ntp * 2 + 1][1] = r3;
            }
            #pragma unroll
            for (int mt = 0; mt < 4; mt++)
                #pragma unroll
                for (int nt = 0; nt < 4; nt++)
                    mma_f16(acc[mt][nt], af[mt][0], af[mt][1], af[mt][2], af[mt][3],
                            bf[nt][0], bf[nt][1]);
        }
    }

    // ---- epilogue: registers -> fp16 global, add bias ----
    const int lr = lane >> 2;           // 0..7
    const int lc = (lane & 3) * 2;      // 0,2,4,6
    #pragma unroll
    for (int mt = 0; mt < 4; mt++) {
        const int rbase = m0 + wm * 64 + mt * 16 + lr;
        #pragma unroll
        for (int nt = 0; nt < 4; nt++) {
            const int lcol = wn * 32 + nt * 8 + lc;
            const int gcol = n0 + lcol;
            const float bx = s_bias[lcol];
            const float by = s_bias[lcol + 1];
            if (rbase < NNODES) {
                __half2 hv = __floats2half2_rn(acc[mt][nt][0] + bx, acc[mt][nt][1] + by);
                *reinterpret_cast<__half2*>(g_ucat_h + (size_t)rbase * NOUT + gcol) = hv;
            }
            if (rbase + 8 < NNODES) {
                __half2 hv = __floats2half2_rn(acc[mt][nt][2] + bx, acc[mt][nt][3] + by);
                *reinterpret_cast<__half2*>(g_ucat_h + (size_t)(rbase + 8) * NOUT + gcol) = hv;
            }
        }
    }
}

// ---------------------------------------------------------------------------
// Edge kernel (fp16 activations): out[e] = b2 + sum_o w2[o]*relu(u[s][o]+v[d][o])
// Four edges per warp-iteration: 8 independent 16B loads in flight per warp.
// ---------------------------------------------------------------------------
__device__ __forceinline__ float edge_dot(uint4 U, uint4 V, float4 w0, float4 w1) {
    float2 u0 = __half22float2(*reinterpret_cast<__half2*>(&U.x));
    float2 u1 = __half22float2(*reinterpret_cast<__half2*>(&U.y));
    float2 u2 = __half22float2(*reinterpret_cast<__half2*>(&U.z));
    float2 u3 = __half22float2(*reinterpret_cast<__half2*>(&U.w));
    float2 v0 = __half22float2(*reinterpret_cast<__half2*>(&V.x));
    float2 v1 = __half22float2(*reinterpret_cast<__half2*>(&V.y));
    float2 v2 = __half22float2(*reinterpret_cast<__half2*>(&V.z));
    float2 v3 = __half22float2(*reinterpret_cast<__half2*>(&V.w));
    float s;
    s  = w0.x * fmaxf(u0.x + v0.x, 0.f);
    s += w0.y * fmaxf(u0.y + v0.y, 0.f);
    s += w0.z * fmaxf(u1.x + v1.x, 0.f);
    s += w0.w * fmaxf(u1.y + v1.y, 0.f);
    s += w1.x * fmaxf(u2.x + v2.x, 0.f);
    s += w1.y * fmaxf(u2.y + v2.y, 0.f);
    s += w1.z * fmaxf(u3.x + v3.x, 0.f);
    s += w1.w * fmaxf(u3.y + v3.y, 0.f);
    return s;
}

__global__ __launch_bounds__(256) void edge_kernel(
    const int* __restrict__ src, const int* __restrict__ dst,
    const float* __restrict__ w2, const float* __restrict__ b2p,
    float* __restrict__ out, int E)
{
    const int lane = threadIdx.x & 31;
    const int warp_global = (blockIdx.x * blockDim.x + threadIdx.x) >> 5;
    const int nwarps = (gridDim.x * blockDim.x) >> 5;

    const float4* w2v = reinterpret_cast<const float4*>(w2);
    float4 w0 = w2v[lane * 2 + 0];
    float4 w1 = w2v[lane * 2 + 1];
    float b2 = *b2p;

    for (int e = warp_global * 4; e < E; e += nwarps * 4) {
        int n_here = min(4, E - e);
        int sx[4], dx[4];
        #pragma unroll
        for (int q = 0; q < 4; q++) {
            int ee = e + ((q < n_here) ? q : 0);
            sx[q] = src[ee];
            dx[q] = dst[ee];
        }

        uint4 U[4], V[4];
        #pragma unroll
        for (int q = 0; q < 4; q++) {
            U[q] = *(reinterpret_cast<const uint4*>(g_ucat_h + (size_t)sx[q] * NOUT) + lane);
            V[q] = *(reinterpret_cast<const uint4*>(g_ucat_h + (size_t)dx[q] * NOUT + NFEAT) + lane);
        }

        float s0 = edge_dot(U[0], V[0], w0, w1);
        float s1 = edge_dot(U[1], V[1], w0, w1);
        float s2 = edge_dot(U[2], V[2], w0, w1);
        float s3 = edge_dot(U[3], V[3], w0, w1);

        #pragma unroll
        for (int o = 16; o > 0; o >>= 1) {
            s0 += __shfl_xor_sync(0xFFFFFFFFu, s0, o);
            s1 += __shfl_xor_sync(0xFFFFFFFFu, s1, o);
            s2 += __shfl_xor_sync(0xFFFFFFFFu, s2, o);
            s3 += __shfl_xor_sync(0xFFFFFFFFu, s3, o);
        }

        if (lane == 0) {
            out[e] = s0 + b2;
            if (n_here > 1) out[e + 1] = s1 + b2;
            if (n_here > 2) out[e + 2] = s2 + b2;
            if (n_here > 3) out[e + 3] = s3 + b2;
        }
    }
}

// ---------------------------------------------------------------------------
// Launch
// ---------------------------------------------------------------------------
extern "C" void kernel_launch(void* const* d_in, const int* in_sizes, int n_in,
                              void* d_out, int out_size)
{
    const float* h    = (const float*)d_in[0];   // [50000, 256]
    const int*   src  = (const int*)  d_in[1];   // [800000]
    const int*   dst  = (const int*)  d_in[2];   // [800000]
    const float* W1_w = (const float*)d_in[3];   // [256, 512]
    const float* W1_b = (const float*)d_in[4];   // [256]
    const float* W2_w = (const float*)d_in[5];   // [256]
    const float* W2_b = (const float*)d_in[6];   // [1]
    float* out = (float*)d_out;
    const int E = in_sizes[1];

    cudaFuncSetAttribute(node_gemm_mma, cudaFuncAttributeMaxDynamicSharedMemorySize, DYN_SMEM);

    // 1) fp32 -> fp16 converts
    conv_h_kernel<<<(NNODES * NFEAT / 2 + 255) / 256, 256>>>(h);
    conv_w_kernel<<<(NOUT * NFEAT + 255) / 256, 256>>>(W1_w);

    // 2) Node GEMM (fp16 HMMA, K=256): g_ucat_h = fp16(h @ Wt^T + b1|0)
    dim3 ggrid(NOUT / NT, (NNODES + MT - 1) / MT);
    node_gemm_mma<<<ggrid, 256, DYN_SMEM>>>(W1_b);

    // 3) Per-edge scores
    edge_kernel<<<2048, 256>>>(src, dst, W2_w, W2_b, out, E);
}